// round 14
// baseline (speedup 1.0000x reference)
#include <cuda_runtime.h>
#include <math.h>
#include <stdint.h>

// VoxelGrid: 8 batches x 100^3, 65536 pts/batch, 10 output channels.
// Structure: bucket = (batch, i, j-decade) -> 8000 slabs of 1000 voxels.
// Pass A bins point INDICES into buckets; pass B accumulates each bucket in
// a 32KB SMEM accumulator and writes its contiguous 40KB output slab.
// No global accumulator, no bitmap, no random DRAM RMW.

#define VGRID   100
#define NBATCH  8
#define NPTS    65536
#define NPOINTS (NBATCH * NPTS)         // 524288
#define NBKT    8000                    // 8*100*10
#define CAP     128                     // slots/bucket (mean 65.5, +7.7 sigma)
#define SLABVOX 1000                    // 10 j-values * 100 k-values
#define COUT    10

// Static scratch. g_cnt is zero at load; pass B re-zeroes its own counter
// each run (graph-replay safe). g_idx never needs cleaning (entries beyond
// the new count are never read).
__device__ uint32_t g_cnt[NBKT];
__device__ int      g_idx[NBKT * CAP];

// ---------------------------------------------------------------------------
// Pass A: bin point indices. 4 points/thread, coords only (3x LDG.128).
// Binning (verified all rounds): idx = floor((c+R)/R), interior bins [1,100].
// ---------------------------------------------------------------------------
__global__ void bin_kernel(const float4* __restrict__ coords4) {
    int t = blockIdx.x * 256 + threadIdx.x;          // < NPOINTS/4
    const float R = 1.0f / 100.0f;

    float4 c0 = coords4[3 * t], c1 = coords4[3 * t + 1], c2 = coords4[3 * t + 2];

    float X[4] = {c0.x, c0.w, c1.z, c2.y};
    float Y[4] = {c0.y, c1.x, c1.w, c2.z};
    float Z[4] = {c0.z, c1.y, c2.x, c2.w};

    int bat = t >> 14;   // a thread's 4 points share one batch

    #pragma unroll
    for (int n = 0; n < 4; n++) {
        int ix = (int)floorf((X[n] + R) / R);
        int iy = (int)floorf((Y[n] + R) / R);
        int iz = (int)floorf((Z[n] + R) / R);
        if (ix < 1 || ix > VGRID || iy < 1 || iy > VGRID ||
            iz < 1 || iz > VGRID)
            continue;                                 // boundary shell dropped
        int bkt = (bat * VGRID + (ix - 1)) * 10 + (iy - 1) / 10;
        uint32_t slot = atomicAdd(&g_cnt[bkt], 1u);
        if (slot < CAP)
            g_idx[bkt * CAP + slot] = 4 * t + n;
    }
}

// ---------------------------------------------------------------------------
// Pass B: one CTA per bucket (8000 CTAs, 512 threads, 32KB static smem).
//  1. zero the 1000-voxel x 8-float smem accumulator
//  2. gather this bucket's points (indices from g_idx, data from inputs in
//     L2), accumulate with smem atomics; re-zero the counter (self-clean)
//  3. write the slab's 2500 contiguous float4s of output directly
//     (means for occupied voxels, index grid everywhere, occupancy flag)
// ---------------------------------------------------------------------------
__global__ void __launch_bounds__(512) slab_kernel(
        const float* __restrict__ coords,
        const float* __restrict__ feats,
        float4* __restrict__ out4) {
    __shared__ float acc[SLABVOX * 8];   // [x,y,z,f0,f1,f2,cnt,pad] per voxel
    __shared__ int s_cnt;

    const int bkt = blockIdx.x;
    const int tid = threadIdx.x;

    #pragma unroll
    for (int q = tid; q < SLABVOX * 8; q += 512)
        acc[q] = 0.f;
    if (tid == 0) {
        uint32_t c = g_cnt[bkt];
        s_cnt = (int)(c < CAP ? c : CAP);
        g_cnt[bkt] = 0u;                 // self-clean for next replay
    }
    __syncthreads();

    const int bat = bkt / 1000;
    const int rem = bkt - bat * 1000;
    const int ii  = rem / 10;            // i index of this slab
    const int jd  = rem - ii * 10;       // j decade

    if (tid < s_cnt) {
        int p = g_idx[bkt * CAP + tid];
        float x  = coords[3 * p], y = coords[3 * p + 1], z = coords[3 * p + 2];
        float f0 = feats [3 * p], f1 = feats[3 * p + 1], f2 = feats[3 * p + 2];
        const float R = 1.0f / 100.0f;
        int iy = (int)floorf((y + R) / R);    // same fp ops as pass A
        int iz = (int)floorf((z + R) / R);
        int L = (iy - 1 - jd * 10) * VGRID + (iz - 1);   // [0,1000)
        float* a = acc + L * 8;
        atomicAdd(a + 0, x);
        atomicAdd(a + 1, y);
        atomicAdd(a + 2, z);
        atomicAdd(a + 3, f0);
        atomicAdd(a + 4, f1);
        atomicAdd(a + 5, f2);
        atomicAdd(a + 6, 1.0f);
    }
    __syncthreads();

    // Output slab: voxels [voxbase, voxbase+1000), 10000 floats contiguous.
    size_t voxbase = ((size_t)(bat * VGRID + ii) * VGRID + jd * 10) * VGRID;
    float4* dst = out4 + (voxbase / 2) * 5;       // voxbase*10/4, exact
    float fi = (float)ii * 0.01f;

    #pragma unroll
    for (int it = 0; it < 5; it++) {
        int f = it * 512 + tid;                   // float4 index in slab
        if (f < SLABVOX * COUT / 4) {             // < 2500
            float vals[4];
            #pragma unroll
            for (int c = 0; c < 4; c++) {
                int gf = 4 * f + c;               // float index in slab
                int L  = gf / 10;                 // voxel in slab
                int ch = gf - 10 * L;             // channel
                float cnt = acc[L * 8 + 6];
                float val;
                if (ch < 6) {
                    val = (cnt > 0.f) ? acc[L * 8 + ch] / cnt : 0.f;
                } else if (ch == 6) {
                    val = fi;
                } else if (ch == 7) {
                    val = (float)(jd * 10 + L / VGRID) * 0.01f;
                } else if (ch == 8) {
                    val = (float)(L - (L / VGRID) * VGRID) * 0.01f;
                } else {
                    val = (cnt > 0.f) ? 1.f : 0.f;
                }
                vals[c] = val;
            }
            dst[f] = make_float4(vals[0], vals[1], vals[2], vals[3]);
        }
    }
}

// ---------------------------------------------------------------------------
extern "C" void kernel_launch(void* const* d_in, const int* in_sizes, int n_in,
                              void* d_out, int out_size) {
    const float4* coords4 = (const float4*)d_in[0];
    const float*  coords  = (const float*)d_in[0];
    const float*  feats   = (const float*)d_in[1];

    bin_kernel <<<NPOINTS / 4 / 256, 256>>>(coords4);
    slab_kernel<<<NBKT, 512>>>(coords, feats, (float4*)d_out);
}